// round 1
// baseline (speedup 1.0000x reference)
#include <cuda_runtime.h>

#define BB 8
#define NN 1024
#define HH 8
#define DD 64
#define CC (HH*DD)   // 512

// Scratch (static device arrays; no allocation in kernel_launch)
__device__ float g_Wh[BB*NN*CC];      // [B,N,H*D] = h @ W
__device__ float g_hp[BB*NN*CC];      // h_prime
__device__ float g_s   [BB*HH*NN];    // a_src  laid out [b][h][n]
__device__ float g_t   [BB*HH*NN];    // a_dst
__device__ float g_es  [BB*HH*NN];    // exp(s)
__device__ float g_es01[BB*HH*NN];    // exp(0.01 s)
__device__ float g_et  [BB*HH*NN];    // exp(t)
__device__ float g_et01[BB*HH*NN];    // exp(0.01 t)
__device__ float g_rZ  [BB*HH*NN];    // 1 / Z[b,h,j]

// ---------------------------------------------------------------------------
// K1: Wh = h @ W      [8192 x 64] @ [64 x 512]
// block: 64 rows x 64 cols, K=64 single pass. grid = (8 col-tiles, 128 row-tiles)
// ---------------------------------------------------------------------------
__global__ __launch_bounds__(256) void k1_wh(const float* __restrict__ h,
                                             const float* __restrict__ W) {
    __shared__ float As[64][65];   // h tile  [row][k]
    __shared__ float Bs[64][65];   // W tile  [k][col]
    int tid = threadIdx.x;
    int r0 = blockIdx.y * 64;
    int c0 = blockIdx.x * 64;
    for (int idx = tid; idx < 4096; idx += 256) {
        int r = idx >> 6, k = idx & 63;
        As[r][k] = h[(r0 + r) * 64 + k];
        Bs[r][k] = W[r * CC + c0 + k];     // r is the k-dim here, k is col
    }
    __syncthreads();
    int tx = tid & 15, ty = tid >> 4;
    float acc[4][4] = {};
#pragma unroll
    for (int k = 0; k < 64; k++) {
        float av[4], bv[4];
#pragma unroll
        for (int r = 0; r < 4; r++) av[r] = As[ty*4+r][k];
#pragma unroll
        for (int c = 0; c < 4; c++) bv[c] = Bs[k][tx*4+c];
#pragma unroll
        for (int r = 0; r < 4; r++)
#pragma unroll
            for (int c = 0; c < 4; c++)
                acc[r][c] = fmaf(av[r], bv[c], acc[r][c]);
    }
#pragma unroll
    for (int r = 0; r < 4; r++)
#pragma unroll
        for (int c = 0; c < 4; c++)
            g_Wh[(r0 + ty*4 + r) * CC + c0 + tx*4 + c] = acc[r][c];
}

// ---------------------------------------------------------------------------
// K2: per (b,n,h): s = Wh[b,n,h,:].a[:64], t = Wh[b,n,h,:].a[64:]
//     store s, t and the 4 exp vectors. 65536 threads.
// ---------------------------------------------------------------------------
__global__ __launch_bounds__(256) void k2_vec(const float* __restrict__ a) {
    __shared__ float as[128];
    if (threadIdx.x < 128) as[threadIdx.x] = a[threadIdx.x];
    __syncthreads();
    int tid = blockIdx.x * 256 + threadIdx.x;           // 0..65535
    int b =  tid >> 13;
    int n = (tid >> 3) & (NN - 1);
    int hh = tid & 7;
    const float4* wh = (const float4*)(g_Wh + (size_t)(b*NN + n)*CC + hh*DD);
    float s = 0.f, t = 0.f;
#pragma unroll
    for (int q = 0; q < 16; q++) {
        float4 v = wh[q];
        s = fmaf(v.x, as[q*4+0], s); s = fmaf(v.y, as[q*4+1], s);
        s = fmaf(v.z, as[q*4+2], s); s = fmaf(v.w, as[q*4+3], s);
        t = fmaf(v.x, as[64+q*4+0], t); t = fmaf(v.y, as[64+q*4+1], t);
        t = fmaf(v.z, as[64+q*4+2], t); t = fmaf(v.w, as[64+q*4+3], t);
    }
    int o = (b*HH + hh)*NN + n;
    g_s[o] = s;  g_t[o] = t;
    g_es[o]   = __expf(s);        g_es01[o] = __expf(0.01f * s);
    g_et[o]   = __expf(t);        g_et01[o] = __expf(0.01f * t);
}

// ---------------------------------------------------------------------------
// K3: Z[b,h,j] = et_j * sum_{i: s_i+t_j>0} es_i  +  et01_j * sum_{else} es01_i
// grid: 256 blocks = 64 (b,h) x 4 j-chunks of 256. Store reciprocal.
// ---------------------------------------------------------------------------
__global__ __launch_bounds__(256) void k3_z() {
    __shared__ float ss[NN], se[NN], se01[NN];
    int bh = blockIdx.x >> 2;
    int chunk = blockIdx.x & 3;
    int base = bh * NN;
    for (int i = threadIdx.x; i < NN; i += 256) {
        ss[i]   = g_s[base + i];
        se[i]   = g_es[base + i];
        se01[i] = g_es01[base + i];
    }
    __syncthreads();
    int j = chunk * 256 + threadIdx.x;
    float tjv    = g_t[base + j];
    float etjv   = g_et[base + j];
    float et01jv = g_et01[base + j];
    float ap = 0.f, an = 0.f;
#pragma unroll 4
    for (int i = 0; i < NN; i++) {
        bool c = (ss[i] + tjv) > 0.f;
        ap += c ? se[i]   : 0.f;
        an += c ? 0.f     : se01[i];
    }
    g_rZ[base + j] = 1.f / fmaf(etjv, ap, et01jv * an);
}

// ---------------------------------------------------------------------------
// K4: fused attention-apply.  For fixed (b,h):
//     h'[i,d] = sum_j E[i,j] * (Wh[j,d] * rZ[j])
//     E[i,j] = (s_i+t_j>0) ? es_i*et_j : es01_i*et01_j   (computed per tile)
// block: 128 i-rows x 64 d-cols, j-tiles of 32. grid = (8 i-tiles, 64 bh)
// ---------------------------------------------------------------------------
__global__ __launch_bounds__(256) void k4_main() {
    constexpr int MT = 128, KT = 32;
    __shared__ float Et[KT][MT + 4];    // E^T  [j][i]
    __shared__ float Vs[KT][DD + 4];    // V' = Wh*rZ  [j][d]
    __shared__ float si[MT], esi[MT], es01i[MT];
    __shared__ float tj[KT], etj[KT], et01j[KT], rzj[KT];

    int bh = blockIdx.y;
    int b = bh >> 3, hh = bh & 7;
    int i0 = blockIdx.x * MT;
    int base = bh * NN;
    int tid = threadIdx.x;

    if (tid < MT) {
        si[tid]    = g_s   [base + i0 + tid];
        esi[tid]   = g_es  [base + i0 + tid];
        es01i[tid] = g_es01[base + i0 + tid];
    }
    int tx = tid & 15, ty = tid >> 4;
    const float* whb = g_Wh + (size_t)(b*NN)*CC + hh*DD;   // + j*CC + d
    float acc[8][4] = {};

    for (int jt = 0; jt < NN; jt += KT) {
        if (tid < KT) {
            int j = base + jt + tid;
            tj[tid]    = g_t[j];
            etj[tid]   = g_et[j];
            et01j[tid] = g_et01[j];
            rzj[tid]   = g_rZ[j];
        }
        __syncthreads();   // tj ready; prev GEMM done -> safe to overwrite Et/Vs

        // fill Vs: 32 x 64 floats = 512 float4, 2 per thread
#pragma unroll
        for (int p = 0; p < 2; p++) {
            int idx = p * 256 + tid;
            int j = idx >> 4, dq = idx & 15;
            float4 v = *(const float4*)(whb + (size_t)(jt + j) * CC + dq * 4);
            float rz = rzj[j];
            float4 o; o.x = v.x*rz; o.y = v.y*rz; o.z = v.z*rz; o.w = v.w*rz;
            *(float4*)&Vs[j][dq * 4] = o;
        }
        // fill Et: 32 x 128 = 4096 elems, 16 per thread
#pragma unroll
        for (int p = 0; p < 16; p++) {
            int idx = p * 256 + tid;
            int j = idx >> 7, i = idx & 127;
            float sum = si[i] + tj[j];
            Et[j][i] = (sum > 0.f) ? esi[i] * etj[j] : es01i[i] * et01j[j];
        }
        __syncthreads();   // tiles ready

#pragma unroll 8
        for (int j = 0; j < KT; j++) {
            float4 e0 = *(const float4*)&Et[j][ty * 8];
            float4 e1 = *(const float4*)&Et[j][ty * 8 + 4];
            float4 v  = *(const float4*)&Vs[j][tx * 4];
            float ev[8] = {e0.x, e0.y, e0.z, e0.w, e1.x, e1.y, e1.z, e1.w};
            float vv[4] = {v.x, v.y, v.z, v.w};
#pragma unroll
            for (int r = 0; r < 8; r++)
#pragma unroll
                for (int c = 0; c < 4; c++)
                    acc[r][c] = fmaf(ev[r], vv[c], acc[r][c]);
        }
    }

    float* outp = g_hp + (size_t)(b*NN + i0 + ty*8) * CC + hh*DD + tx*4;
#pragma unroll
    for (int r = 0; r < 8; r++) {
        float4 o = {acc[r][0], acc[r][1], acc[r][2], acc[r][3]};
        *(float4*)(outp + (size_t)r * CC) = o;
    }
}

// ---------------------------------------------------------------------------
// K5: out = h_prime @ out_W + out_b    [8192 x 512] @ [512 x 64]
// block: 64 rows x 64 cols, K in 8 tiles of 64. grid = 128 blocks.
// ---------------------------------------------------------------------------
__global__ __launch_bounds__(256) void k5_out(const float* __restrict__ oW,
                                              const float* __restrict__ ob,
                                              float* __restrict__ out) {
    __shared__ float As[64][65];
    __shared__ float Bs[64][65];
    int tid = threadIdx.x;
    int r0 = blockIdx.x * 64;
    int tx = tid & 15, ty = tid >> 4;
    float acc[4][4] = {};
    for (int kt = 0; kt < CC; kt += 64) {
        __syncthreads();
        for (int idx = tid; idx < 4096; idx += 256) {
            int r = idx >> 6, k = idx & 63;
            As[r][k] = g_hp[(size_t)(r0 + r) * CC + kt + k];
            Bs[r][k] = oW[(size_t)(kt + r) * DD + k];
        }
        __syncthreads();
#pragma unroll
        for (int k = 0; k < 64; k++) {
            float av[4], bv[4];
#pragma unroll
            for (int r = 0; r < 4; r++) av[r] = As[ty*4+r][k];
#pragma unroll
            for (int c = 0; c < 4; c++) bv[c] = Bs[k][tx*4+c];
#pragma unroll
            for (int r = 0; r < 4; r++)
#pragma unroll
                for (int c = 0; c < 4; c++)
                    acc[r][c] = fmaf(av[r], bv[c], acc[r][c]);
        }
    }
#pragma unroll
    for (int r = 0; r < 4; r++)
#pragma unroll
        for (int c = 0; c < 4; c++)
            out[(size_t)(r0 + ty*4 + r) * DD + tx*4 + c] = acc[r][c] + ob[tx*4+c];
}

// ---------------------------------------------------------------------------
extern "C" void kernel_launch(void* const* d_in, const int* in_sizes, int n_in,
                              void* d_out, int out_size) {
    const float* h    = (const float*)d_in[0];   // [8,1024,64]
    // d_in[1] = adj, unused by the module
    const float* W    = (const float*)d_in[2];   // [64,512]
    const float* a    = (const float*)d_in[3];   // [128,1]
    const float* oW   = (const float*)d_in[4];   // [512,64]
    const float* ob   = (const float*)d_in[5];   // [64]
    float* out = (float*)d_out;                  // [8,1024,64]

    k1_wh <<<dim3(CC/64, (BB*NN)/64), 256>>>(h, W);
    k2_vec<<<(BB*NN*HH)/256, 256>>>(a);
    k3_z  <<<BB*HH*4, 256>>>();
    k4_main<<<dim3(NN/128, BB*HH), 256>>>();
    k5_out<<<(BB*NN)/64, 256>>>(oW, ob, out);
}

// round 3
// speedup vs baseline: 2.5053x; 2.5053x over previous
#include <cuda_runtime.h>
#include <cuda_bf16.h>
#include <cstdint>

#define BB 8
#define NN 1024
#define HH 8
#define DD 64
#define CC (HH*DD)   // 512

// Scratch
__device__ float g_Wh[BB*NN*CC];
__device__ float g_hp[BB*NN*CC];
__device__ float g_es  [BB*HH*NN];
__device__ float g_es01[BB*HH*NN];
__device__ float g_et  [BB*HH*NN];
__device__ float g_et01[BB*HH*NN];
__device__ float g_rZ  [BB*HH*NN];

__device__ __forceinline__ uint32_t smem_u32(const void* p) {
    uint32_t a;
    asm("{ .reg .u64 t; cvta.to.shared.u64 t, %1; cvt.u32.u64 %0, t; }" : "=r"(a) : "l"(p));
    return a;
}

#define LDSM_T4(r0, r1, r2, r3, addr) \
    asm volatile("ldmatrix.sync.aligned.m8n8.x4.trans.shared.b16 {%0,%1,%2,%3}, [%4];" \
                 : "=r"(r0), "=r"(r1), "=r"(r2), "=r"(r3) : "r"(addr))

#define MMA16816(d0,d1,d2,d3, a0,a1,a2,a3, b0,b1) \
    asm volatile("mma.sync.aligned.m16n8k16.row.col.f32.bf16.bf16.f32 " \
                 "{%0,%1,%2,%3}, {%4,%5,%6,%7}, {%8,%9}, {%0,%1,%2,%3};" \
                 : "+f"(d0), "+f"(d1), "+f"(d2), "+f"(d3) \
                 : "r"(a0), "r"(a1), "r"(a2), "r"(a3), "r"(b0), "r"(b1))

__device__ __forceinline__ uint32_t pack_bf16(float a, float b) {
    __nv_bfloat162 t = __floats2bfloat162_rn(a, b);
    return *(uint32_t*)&t;
}
// hi/lo split of a pair: returns packed hi, writes packed lo
__device__ __forceinline__ uint32_t split_pair(float e0, float e1, uint32_t& lo) {
    float h0 = __bfloat162float(__float2bfloat16_rn(e0));
    float h1 = __bfloat162float(__float2bfloat16_rn(e1));
    lo = pack_bf16(e0 - h0, e1 - h1);
    return pack_bf16(h0, h1);
}

// ---------------------------------------------------------------------------
// K1: Wh = h @ W      [8192 x 64] @ [64 x 512]
// ---------------------------------------------------------------------------
__global__ __launch_bounds__(256) void k1_wh(const float* __restrict__ h,
                                             const float* __restrict__ W) {
    __shared__ float As[64][65];
    __shared__ float Bs[64][65];
    int tid = threadIdx.x;
    int r0 = blockIdx.y * 64;
    int c0 = blockIdx.x * 64;
    for (int idx = tid; idx < 4096; idx += 256) {
        int r = idx >> 6, k = idx & 63;
        As[r][k] = h[(r0 + r) * 64 + k];
        Bs[r][k] = W[r * CC + c0 + k];
    }
    __syncthreads();
    int tx = tid & 15, ty = tid >> 4;
    float acc[4][4] = {};
#pragma unroll
    for (int k = 0; k < 64; k++) {
        float av[4], bv[4];
#pragma unroll
        for (int r = 0; r < 4; r++) av[r] = As[ty*4+r][k];
#pragma unroll
        for (int c = 0; c < 4; c++) bv[c] = Bs[k][tx*4+c];
#pragma unroll
        for (int r = 0; r < 4; r++)
#pragma unroll
            for (int c = 0; c < 4; c++)
                acc[r][c] = fmaf(av[r], bv[c], acc[r][c]);
    }
#pragma unroll
    for (int r = 0; r < 4; r++)
#pragma unroll
        for (int c = 0; c < 4; c++)
            g_Wh[(r0 + ty*4 + r) * CC + c0 + tx*4 + c] = acc[r][c];
}

// ---------------------------------------------------------------------------
// K2: per (b,n,h) dot products with a -> 4 exp vectors
// ---------------------------------------------------------------------------
__global__ __launch_bounds__(256) void k2_vec(const float* __restrict__ a) {
    __shared__ float as[128];
    if (threadIdx.x < 128) as[threadIdx.x] = a[threadIdx.x];
    __syncthreads();
    int tid = blockIdx.x * 256 + threadIdx.x;
    int b =  tid >> 13;
    int n = (tid >> 3) & (NN - 1);
    int hh = tid & 7;
    const float4* wh = (const float4*)(g_Wh + (size_t)(b*NN + n)*CC + hh*DD);
    float s = 0.f, t = 0.f;
#pragma unroll
    for (int q = 0; q < 16; q++) {
        float4 v = wh[q];
        s = fmaf(v.x, as[q*4+0], s); s = fmaf(v.y, as[q*4+1], s);
        s = fmaf(v.z, as[q*4+2], s); s = fmaf(v.w, as[q*4+3], s);
        t = fmaf(v.x, as[64+q*4+0], t); t = fmaf(v.y, as[64+q*4+1], t);
        t = fmaf(v.z, as[64+q*4+2], t); t = fmaf(v.w, as[64+q*4+3], t);
    }
    int o = (b*HH + hh)*NN + n;
    g_es[o]   = __expf(s);        g_es01[o] = __expf(0.01f * s);
    g_et[o]   = __expf(t);        g_et01[o] = __expf(0.01f * t);
}

// ---------------------------------------------------------------------------
// K3: Z[b,h,j] = sum_i max(es_i*et_j, es01_i*et01_j); store 1/Z
// (exp(leaky_relu(s+t)) == max(e^s e^t, e^{0.01s} e^{0.01t}) exactly, by
//  monotonicity of exp)
// ---------------------------------------------------------------------------
__global__ __launch_bounds__(256) void k3_z() {
    __shared__ float se[NN], se01[NN];
    int bh = blockIdx.x >> 2;
    int chunk = blockIdx.x & 3;
    int base = bh * NN;
    for (int i = threadIdx.x; i < NN; i += 256) {
        se[i]   = g_es[base + i];
        se01[i] = g_es01[base + i];
    }
    __syncthreads();
    int j = chunk * 256 + threadIdx.x;
    float etjv   = g_et[base + j];
    float et01jv = g_et01[base + j];
    float acc = 0.f;
#pragma unroll 4
    for (int i = 0; i < NN; i++)
        acc += fmaxf(se[i] * etjv, se01[i] * et01jv);
    g_rZ[base + j] = 1.f / acc;
}

// ---------------------------------------------------------------------------
// K4: tensor-core fused attention-apply via mma.sync (bf16 hi/lo, fp32 acc).
//   h'[i,:] = sum_j E[i,j] * V'[j,:],  E = max(es_i*et_j, es01_i*et01_j),
//   V'[j,:] = Wh[j,:] * rZ_j.
// CTA = 128 i-rows of one (b,h); 8 warps, warp w owns rows [16w,16w+16).
// A (E) fragments are computed directly in registers (no smem round trip).
// B (V') staged hi/lo in smem, loaded with ldmatrix.x4.trans.
// ---------------------------------------------------------------------------
__global__ __launch_bounds__(256) void k4_mma() {
    __shared__ __align__(16) __nv_bfloat16 Vh[32][72];   // padded: stride 144B
    __shared__ __align__(16) __nv_bfloat16 Vl[32][72];
    __shared__ float etj[32], et01j[32];

    int tid = threadIdx.x;
    int lane = tid & 31, w = tid >> 5;
    int bh = blockIdx.y;
    int b = bh >> 3, hh = bh & 7;
    int i0 = blockIdx.x * 128;
    int base = bh * NN;

    const float* whb = g_Wh + (size_t)(b * NN) * CC + hh * DD;

    // per-lane A rows
    int gr = lane >> 2;            // 0..7
    int ctg2 = (lane & 3) * 2;     // k pair base
    int r0 = i0 + w * 16 + gr;
    float es0   = g_es  [base + r0];
    float es01_0 = g_es01[base + r0];
    float es1   = g_es  [base + r0 + 8];
    float es01_1 = g_es01[base + r0 + 8];

    // V fill decomposition
    int bj = tid >> 3;             // 0..31 (j row)
    int bd = (tid & 7) * 8;        // d group

    // ldmatrix source address (per lane), c-dependent part added in loop
    uint32_t vh_base = smem_u32(Vh) + ((lane & 15) * 72 + (lane >> 4) * 8) * 2;
    uint32_t vl_base = smem_u32(Vl) + ((lane & 15) * 72 + (lane >> 4) * 8) * 2;

    float acc[8][4] = {};   // [n8 tile][reg]

    for (int chunk = 0; chunk < 32; chunk++) {
        int jt = chunk * 32;
        __syncthreads();   // prior chunk's ldmatrix/etj reads complete
        if (tid < 32) {
            etj[tid]   = g_et  [base + jt + tid];
            et01j[tid] = g_et01[base + jt + tid];
        }
        // ---- V' fill: hi/lo split of Wh[jt+bj, bd..bd+7] * rZ ----
        {
            float rz = g_rZ[base + jt + bj];
            const float* src = whb + (size_t)(jt + bj) * CC + bd;
            float4 v0 = *(const float4*)(src);
            float4 v1 = *(const float4*)(src + 4);
            float f[8] = {v0.x*rz, v0.y*rz, v0.z*rz, v0.w*rz,
                          v1.x*rz, v1.y*rz, v1.z*rz, v1.w*rz};
            uint32_t lo0, lo1, lo2, lo3;
            uint32_t h0 = split_pair(f[0], f[1], lo0);
            uint32_t h1 = split_pair(f[2], f[3], lo1);
            uint32_t h2 = split_pair(f[4], f[5], lo2);
            uint32_t h3 = split_pair(f[6], f[7], lo3);
            uint4 ph = {h0, h1, h2, h3};
            uint4 pl = {lo0, lo1, lo2, lo3};
            *(uint4*)&Vh[bj][bd] = ph;
            *(uint4*)&Vl[bj][bd] = pl;
        }
        __syncthreads();

#pragma unroll
        for (int c = 0; c < 2; c++) {
            // ---- A (E) fragments directly in registers ----
            int kb = c * 16 + ctg2;
            float et_0 = etj[kb],     et01_0v = et01j[kb];
            float et_1 = etj[kb + 1], et01_1v = et01j[kb + 1];
            float et_8 = etj[kb + 8], et01_8v = et01j[kb + 8];
            float et_9 = etj[kb + 9], et01_9v = et01j[kb + 9];

            uint32_t ah0, ah1, ah2, ah3, al0, al1, al2, al3;
            ah0 = split_pair(fmaxf(es0*et_0, es01_0*et01_0v),
                             fmaxf(es0*et_1, es01_0*et01_1v), al0);
            ah1 = split_pair(fmaxf(es1*et_0, es01_1*et01_0v),
                             fmaxf(es1*et_1, es01_1*et01_1v), al1);
            ah2 = split_pair(fmaxf(es0*et_8, es01_0*et01_8v),
                             fmaxf(es0*et_9, es01_0*et01_9v), al2);
            ah3 = split_pair(fmaxf(es1*et_8, es01_1*et01_8v),
                             fmaxf(es1*et_9, es01_1*et01_9v), al3);

            uint32_t coff = (uint32_t)(c * 16 * 72 * 2);
#pragma unroll
            for (int t = 0; t < 4; t++) {
                uint32_t bh0, bh1, bh2, bh3, bl0, bl1, bl2, bl3;
                LDSM_T4(bh0, bh1, bh2, bh3, vh_base + coff + t * 32);
                LDSM_T4(bl0, bl1, bl2, bl3, vl_base + coff + t * 32);
                // n8 tiles 2t and 2t+1
                MMA16816(acc[2*t][0], acc[2*t][1], acc[2*t][2], acc[2*t][3],
                         ah0, ah1, ah2, ah3, bh0, bh1);
                MMA16816(acc[2*t+1][0], acc[2*t+1][1], acc[2*t+1][2], acc[2*t+1][3],
                         ah0, ah1, ah2, ah3, bh2, bh3);
                MMA16816(acc[2*t][0], acc[2*t][1], acc[2*t][2], acc[2*t][3],
                         ah0, ah1, ah2, ah3, bl0, bl1);
                MMA16816(acc[2*t+1][0], acc[2*t+1][1], acc[2*t+1][2], acc[2*t+1][3],
                         ah0, ah1, ah2, ah3, bl2, bl3);
                MMA16816(acc[2*t][0], acc[2*t][1], acc[2*t][2], acc[2*t][3],
                         al0, al1, al2, al3, bh0, bh1);
                MMA16816(acc[2*t+1][0], acc[2*t+1][1], acc[2*t+1][2], acc[2*t+1][3],
                         al0, al1, al2, al3, bh2, bh3);
            }
        }
    }

    // Epilogue: accumulator (m16n8 layout) -> g_hp
    float* dst0 = g_hp + (size_t)(b * NN + r0) * CC + hh * DD + ctg2;
    float* dst1 = dst0 + (size_t)8 * CC;   // row r0+8
#pragma unroll
    for (int t = 0; t < 8; t++) {
        float2 o0 = {acc[t][0], acc[t][1]};
        float2 o1 = {acc[t][2], acc[t][3]};
        *(float2*)(dst0 + t * 8) = o0;
        *(float2*)(dst1 + t * 8) = o1;
    }
}

// ---------------------------------------------------------------------------
// K5: out = h_prime @ out_W + out_b    [8192 x 512] @ [512 x 64]
// ---------------------------------------------------------------------------
__global__ __launch_bounds__(256) void k5_out(const float* __restrict__ oW,
                                              const float* __restrict__ ob,
                                              float* __restrict__ out) {
    __shared__ float As[64][65];
    __shared__ float Bs[64][65];
    int tid = threadIdx.x;
    int r0 = blockIdx.x * 64;
    int tx = tid & 15, ty = tid >> 4;
    float acc[4][4] = {};
    for (int kt = 0; kt < CC; kt += 64) {
        __syncthreads();
        for (int idx = tid; idx < 4096; idx += 256) {
            int r = idx >> 6, k = idx & 63;
            As[r][k] = g_hp[(size_t)(r0 + r) * CC + kt + k];
            Bs[r][k] = oW[(size_t)(kt + r) * DD + k];
        }
        __syncthreads();
#pragma unroll
        for (int k = 0; k < 64; k++) {
            float av[4], bv[4];
#pragma unroll
            for (int r = 0; r < 4; r++) av[r] = As[ty*4+r][k];
#pragma unroll
            for (int c = 0; c < 4; c++) bv[c] = Bs[k][tx*4+c];
#pragma unroll
            for (int r = 0; r < 4; r++)
#pragma unroll
                for (int c = 0; c < 4; c++)
                    acc[r][c] = fmaf(av[r], bv[c], acc[r][c]);
        }
    }
#pragma unroll
    for (int r = 0; r < 4; r++)
#pragma unroll
        for (int c = 0; c < 4; c++)
            out[(size_t)(r0 + ty*4 + r) * DD + tx*4 + c] = acc[r][c] + ob[tx*4+c];
}

// ---------------------------------------------------------------------------
extern "C" void kernel_launch(void* const* d_in, const int* in_sizes, int n_in,
                              void* d_out, int out_size) {
    const float* h    = (const float*)d_in[0];
    const float* W    = (const float*)d_in[2];
    const float* a    = (const float*)d_in[3];
    const float* oW   = (const float*)d_in[4];
    const float* ob   = (const float*)d_in[5];
    float* out = (float*)d_out;

    k1_wh <<<dim3(CC/64, (BB*NN)/64), 256>>>(h, W);
    k2_vec<<<(BB*NN*HH)/256, 256>>>(a);
    k3_z  <<<BB*HH*4, 256>>>();
    k4_mma<<<dim3(NN/128, BB*HH), 256>>>();
    k5_out<<<(BB*NN)/64, 256>>>(oW, ob, out);
}